// round 12
// baseline (speedup 1.0000x reference)
#include <cuda_runtime.h>
#include <cuda_fp16.h>
#include <cstdint>

// ---------------- problem constants ----------------
#define N_ROWS 16384
#define DF     128
#define KC     32                 // K chunk per ring stage
#define NITER  (N_ROWS / KC)      // 512
#define NPITER (NITER / 2)        // 256 stage-pairs
#define NPAIR  4                  // A ring = 4 pairs = 8 stages

// g_XWf: XW = x@W, fp16 pairs, fragment-plane layout per 32-k chunk (2048 u32 = 8KB):
//   chunk c, block (h,ks) = (h*2+ks)*512 u32; plane j (0..3) * 128; lane*4 + (ni&3)
//   j = jh*2 + (ni>>2), jh: 0 = b0 (pair rows ks*8+tg), 1 = b1 (pair rows ks*8+4+tg)
//   lane = 4*g + tg ; value = half2{XW[2p][n], XW[2p+1][n]}, n = h*64+ni*8+g
__device__ uint32_t g_XWf[(size_t)NITER * 2048];   // 4 MiB (L2-resident)

__device__ __forceinline__ uint32_t packh2(float lo, float hi) {
    __half2 h = __floats2half2_rn(lo, hi);
    return *(uint32_t*)&h;
}
__device__ __forceinline__ void bar_sync_named(int id) {
    asm volatile("bar.sync %0, 512;" :: "r"(id) : "memory");
}
__device__ __forceinline__ void bar_arrive_named(int id) {
    asm volatile("bar.arrive %0, 512;" :: "r"(id) : "memory");
}
// barrier ids: FULL(p)=1+p (1..4), EMPTY(p)=5+p (5..8)

// ---------------- kernel 1: XW = x @ W, emitted in fragment-plane order ----------------
#define XW_SMEM ((128 * 132 + 128 * 128) * 4)

__global__ void __launch_bounds__(256) xw_kernel(const float* __restrict__ x,
                                                 const float* __restrict__ W) {
    extern __shared__ float sm_xw[];
    float* xsT = sm_xw;              // [128][132] transposed x tile
    float* Ws  = sm_xw + 128 * 132;  // [128][128]
    uint32_t* stage = (uint32_t*)sm_xw;  // 8192 u32 staging (reused after compute)
    const int tid = threadIdx.x;
    const int j0 = blockIdx.x * 128;

    for (int idx = tid; idx < 128 * 128; idx += 256) {
        int j = idx >> 7, k = idx & 127;
        xsT[k * 132 + j] = x[(size_t)(j0 + j) * DF + k];
        Ws[idx] = W[idx];
    }
    __syncthreads();

    const int tx = tid & 15, ty = tid >> 4;
    const int jb = ty * 8, db = tx * 8;
    float acc[8][8];
#pragma unroll
    for (int a = 0; a < 8; a++)
#pragma unroll
        for (int b = 0; b < 8; b++) acc[a][b] = 0.0f;

    for (int k = 0; k < 128; k++) {
        float4 a0 = *(const float4*)(xsT + k * 132 + jb);
        float4 a1 = *(const float4*)(xsT + k * 132 + jb + 4);
        float4 b0 = *(const float4*)(Ws + k * 128 + db);
        float4 b1 = *(const float4*)(Ws + k * 128 + db + 4);
        float aa[8] = {a0.x, a0.y, a0.z, a0.w, a1.x, a1.y, a1.z, a1.w};
        float bb[8] = {b0.x, b0.y, b0.z, b0.w, b1.x, b1.y, b1.z, b1.w};
#pragma unroll
        for (int jj = 0; jj < 8; jj++)
#pragma unroll
            for (int dd = 0; dd < 8; dd++) acc[jj][dd] += aa[jj] * bb[dd];
    }
    __syncthreads();   // done reading xsT/Ws; reuse as staging

    // scatter into fragment-plane staging: this CTA covers 64 pair-rows = 4 chunks
#pragma unroll
    for (int q = 0; q < 4; q++) {
        const int p_local = (jb >> 1) + q;          // 0..63
        const int c_local = p_local >> 4;           // chunk 0..3
        const int kk = p_local & 15;
        const int ks = kk >> 3, r8 = kk & 7;
        const int jh = r8 >> 2, tg = r8 & 3;
#pragma unroll
        for (int dd = 0; dd < 8; dd++) {
            const int n = db + dd;
            const int h = n >> 6, ni = (n >> 3) & 7, g = n & 7;
            const int lane = 4 * g + tg;
            const int j = jh * 2 + (ni >> 2);
            const int off = c_local * 2048 + (h * 2 + ks) * 512 + j * 128
                          + lane * 4 + (ni & 3);
            stage[off] = packh2(acc[2 * q][dd], acc[2 * q + 1][dd]);
        }
    }
    __syncthreads();

    // linear coalesced copy to global (4 chunks = 8192 u32 = 2048 uint4)
    uint4* dst = (uint4*)(g_XWf + (size_t)blockIdx.x * 8192);
    const uint4* srcv = (const uint4*)stage;
#pragma unroll
    for (int i = 0; i < 8; i++) dst[tid + i * 256] = srcv[tid + i * 256];
}

// ---------------- kernel 2: warp-specialized fused exp + softmax-GEMM ----------------
// 512 threads: tid<256 = MMA consumers (8 warps), tid>=256 = producers (A only).
// A ring: 8 stages (4 pairs) x [128 rows x 20 u32 fp16-pairs] = 10240B each.
// B: direct LDG.128 from L2-resident g_XWf planes (coalesced), register-pipelined.
#define SA2 20
#define A_STG_B  (128 * SA2 * 4)                 // 10240
#define A_OFF    0u
#define RS_OFF   (A_OFF + 8 * A_STG_B)           // 81920
#define BIAS_OFF (RS_OFF + 512)                  // 82432
#define FUSED_SMEM (BIAS_OFF + 512)              // 82944

__global__ void __launch_bounds__(512, 1) fused_kernel(const float* __restrict__ adj,
                                                       const float* __restrict__ bias,
                                                       float* __restrict__ out) {
    extern __shared__ char sm8[];
    float* rs = (float*)(sm8 + RS_OFF);
    float* bs = (float*)(sm8 + BIAS_OFF);

    const int tid = threadIdx.x;
    const int m0 = blockIdx.x * 128;

    if (tid < DF) bs[tid] = bias[tid];

    if (tid >= 256) {
        // ================= PRODUCERS (adj -> exp -> A ring) =================
        const int ptid = tid - 256;
        const int r = ptid >> 1;           // adj row within tile
        const int hf = ptid & 1;           // 16-float half of 32-col chunk
        const float* agsrc = adj + (size_t)(m0 + r) * N_ROWS + hf * 16;
        const uint32_t a_sts = (uint32_t)r * SA2 + hf * 8;   // u32 units

        float4 a0b[4], a1b[4];
        float rsum = 0.0f;

#define LDGA(cn, BUF) do {                                                       \
            const float* _p = agsrc + (size_t)(cn) * KC;                         \
            BUF[0] = *(const float4*)(_p);                                       \
            BUF[1] = *(const float4*)(_p + 4);                                   \
            BUF[2] = *(const float4*)(_p + 8);                                   \
            BUF[3] = *(const float4*)(_p + 12);                                  \
        } while (0)
#define STSA(BUF, S) do {                                                        \
            uint32_t pk[8];                                                      \
            _Pragma("unroll")                                                    \
            for (int q = 0; q < 4; q++) {                                        \
                float e0 = __expf(BUF[q].x), e1 = __expf(BUF[q].y);              \
                float e2 = __expf(BUF[q].z), e3 = __expf(BUF[q].w);              \
                rsum += (e0 + e1) + (e2 + e3);                                   \
                pk[2 * q]     = packh2(e0, e1);                                  \
                pk[2 * q + 1] = packh2(e2, e3);                                  \
            }                                                                    \
            uint32_t* As = (uint32_t*)(sm8 + A_OFF + (size_t)(S) * A_STG_B);     \
            *(uint4*)(As + a_sts)     = make_uint4(pk[0], pk[1], pk[2], pk[3]);  \
            *(uint4*)(As + a_sts + 4) = make_uint4(pk[4], pk[5], pk[6], pk[7]);  \
        } while (0)

        LDGA(0, a0b);
        LDGA(1, a1b);

        int p = 0;
        for (int pt = 0; pt < NPITER; ++pt) {
            if (pt >= NPAIR) bar_sync_named(5 + p);   // pair p slots free
            const int c0 = 2 * pt;
            STSA(a0b, 2 * p);
            if (c0 + 2 < NITER) LDGA(c0 + 2, a0b);
            STSA(a1b, 2 * p + 1);
            if (c0 + 3 < NITER) LDGA(c0 + 3, a1b);
            __threadfence_block();
            bar_arrive_named(1 + p);
            p = (p == NPAIR - 1) ? 0 : p + 1;
        }

        rsum += __shfl_xor_sync(0xffffffffu, rsum, 1);
        if (hf == 0) rs[r] = rsum;
        __syncthreads();
        // producers done (consumers do epilogue)
    } else {
        // ================= CONSUMERS =================
        const int wid = tid >> 5;
        const int lid = tid & 31;
        const int g = lid >> 2, tg = lid & 3;
        const int mB = (wid & 3) * 32;
        const int h  = wid >> 2;
        const int nB = h * 64;

        float acc[2][8][4];
#pragma unroll
        for (int i = 0; i < 2; i++)
#pragma unroll
            for (int j = 0; j < 8; j++)
#pragma unroll
                for (int c = 0; c < 4; c++) acc[i][j][c] = 0.0f;

        // B register pipeline: 2 buffers of 4 uint4; load half (c, ks)
        uint4 bq[2][4];
#define LDB(BUF, c, ks) do {                                                     \
            const uint4* _bp = (const uint4*)g_XWf + (size_t)(c) * 512           \
                               + ((h) * 2 + (ks)) * 128 + lid;                   \
            BUF[0] = __ldg(_bp);                                                 \
            BUF[1] = __ldg(_bp + 32);                                            \
            BUF[2] = __ldg(_bp + 64);                                            \
            BUF[3] = __ldg(_bp + 96);                                            \
        } while (0)

        LDB(bq[0], 0, 0);   // prologue: half index 0

        int p = 0;
        for (int pt = 0; pt < NPITER; ++pt) {
            bar_sync_named(1 + p);
#pragma unroll
            for (int half = 0; half < 2; half++) {
                const int it = 2 * pt + half;
                const int s = 2 * p + half;
                const uint32_t* As = (const uint32_t*)(sm8 + A_OFF + (size_t)s * A_STG_B);
#pragma unroll
                for (int ks = 0; ks < 2; ks++) {
                    const int hIdx = it * 2 + ks;
                    const int cur = hIdx & 1;
                    // prefetch next ks-half (distance 1)
                    int nh = hIdx + 1;
                    if (nh > 2 * NITER - 1) nh = 2 * NITER - 1;
                    LDB(bq[cur ^ 1], nh >> 1, nh & 1);

                    // A fragments (scalar LDS, conflict-free via SA2=20)
                    uint32_t af[2][4];
#pragma unroll
                    for (int mi = 0; mi < 2; mi++) {
                        const uint32_t* Ar = As + (mB + mi * 16 + g) * SA2 + ks * 8 + tg;
                        af[mi][0] = Ar[0];
                        af[mi][1] = Ar[8 * SA2];
                        af[mi][2] = Ar[4];
                        af[mi][3] = Ar[8 * SA2 + 4];
                    }
                    const uint32_t b0a[8] = {bq[cur][0].x, bq[cur][0].y, bq[cur][0].z, bq[cur][0].w,
                                             bq[cur][1].x, bq[cur][1].y, bq[cur][1].z, bq[cur][1].w};
                    const uint32_t b1a[8] = {bq[cur][2].x, bq[cur][2].y, bq[cur][2].z, bq[cur][2].w,
                                             bq[cur][3].x, bq[cur][3].y, bq[cur][3].z, bq[cur][3].w};
#pragma unroll
                    for (int ni = 0; ni < 8; ni++) {
#pragma unroll
                        for (int mi = 0; mi < 2; mi++) {
                            asm volatile(
                                "mma.sync.aligned.m16n8k16.row.col.f32.f16.f16.f32 "
                                "{%0,%1,%2,%3}, {%4,%5,%6,%7}, {%8,%9}, {%0,%1,%2,%3};"
                                : "+f"(acc[mi][ni][0]), "+f"(acc[mi][ni][1]),
                                  "+f"(acc[mi][ni][2]), "+f"(acc[mi][ni][3])
                                : "r"(af[mi][0]), "r"(af[mi][1]), "r"(af[mi][2]), "r"(af[mi][3]),
                                  "r"(b0a[ni]), "r"(b1a[ni]));
                        }
                    }
                }
            }
            bar_arrive_named(5 + p);
            p = (p == NPAIR - 1) ? 0 : p + 1;
        }

        __syncthreads();   // rowsums + bias visible

        // epilogue: divide + bias + store
#pragma unroll
        for (int mi = 0; mi < 2; mi++) {
            const int r0 = mB + mi * 16 + g;
            const int r1 = r0 + 8;
            const float inv0 = 1.0f / rs[r0];
            const float inv1 = 1.0f / rs[r1];
#pragma unroll
            for (int ni = 0; ni < 8; ni++) {
                const int c = nB + ni * 8 + 2 * tg;
                const float b0v = bs[c];
                const float b1v = bs[c + 1];
                float2 o;
                o.x = acc[mi][ni][0] * inv0 + b0v;
                o.y = acc[mi][ni][1] * inv0 + b1v;
                *(float2*)(out + (size_t)(m0 + r0) * DF + c) = o;
                o.x = acc[mi][ni][2] * inv1 + b0v;
                o.y = acc[mi][ni][3] * inv1 + b1v;
                *(float2*)(out + (size_t)(m0 + r1) * DF + c) = o;
            }
        }
    }
}

// ---------------- launcher ----------------
extern "C" void kernel_launch(void* const* d_in, const int* in_sizes, int n_in,
                              void* d_out, int out_size) {
    const float* x   = (const float*)d_in[0];
    const float* adj = (const float*)d_in[1];
    const float* W   = (const float*)d_in[2];
    const float* b   = (const float*)d_in[3];
    float* out = (float*)d_out;
    (void)in_sizes; (void)n_in; (void)out_size;

    cudaFuncSetAttribute(xw_kernel, cudaFuncAttributeMaxDynamicSharedMemorySize, XW_SMEM);
    cudaFuncSetAttribute(fused_kernel, cudaFuncAttributeMaxDynamicSharedMemorySize, FUSED_SMEM);

    xw_kernel<<<N_ROWS / 128, 256, XW_SMEM>>>(x, W);
    fused_kernel<<<N_ROWS / 128, 512, FUSED_SMEM>>>(adj, b, out);
}

// round 13
// speedup vs baseline: 1.0024x; 1.0024x over previous
#include <cuda_runtime.h>
#include <cuda_fp16.h>
#include <cstdint>

// ---------------- problem constants ----------------
#define N_ROWS 16384
#define DF     128
#define KC     32                 // K chunk per ring stage
#define NITER  (N_ROWS / KC)      // 512
#define NPITER (NITER / 2)        // 256 stage-pairs
#define NPAIR  4                  // A ring = 4 pairs = 8 stages

// g_XWf: XW = x@W, fp16 pairs, fragment-plane layout per 32-k chunk (2048 u32 = 8KB):
//   chunk c, block (h,ks) = (h*2+ks)*512 u32; plane j (0..3) * 128; lane*4 + (ni&3)
//   j = jh*2 + (ni>>2), jh: 0 = b0 (pair rows ks*8+tg), 1 = b1 (pair rows ks*8+4+tg)
//   lane = 4*g + tg ; value = half2{XW[2p][n], XW[2p+1][n]}, n = h*64+ni*8+g
__device__ uint32_t g_XWf[(size_t)NITER * 2048];   // 4 MiB (L2-resident)

__device__ __forceinline__ uint32_t packh2(float lo, float hi) {
    __half2 h = __floats2half2_rn(lo, hi);
    return *(uint32_t*)&h;
}
__device__ __forceinline__ void bar_sync_named(int id) {
    asm volatile("bar.sync %0, 512;" :: "r"(id) : "memory");
}
__device__ __forceinline__ void bar_arrive_named(int id) {
    asm volatile("bar.arrive %0, 512;" :: "r"(id) : "memory");
}
// barrier ids: FULL(p)=1+p (1..4), EMPTY(p)=5+p (5..8)

// ---------------- kernel 1: XW = x @ W, emitted in fragment-plane order ----------------
#define XW_SMEM ((128 * 132 + 128 * 128) * 4)

__global__ void __launch_bounds__(256) xw_kernel(const float* __restrict__ x,
                                                 const float* __restrict__ W) {
    extern __shared__ float sm_xw[];
    float* xsT = sm_xw;              // [128][132] transposed x tile
    float* Ws  = sm_xw + 128 * 132;  // [128][128]
    uint32_t* stage = (uint32_t*)sm_xw;  // 8192 u32 staging (reused after compute)
    const int tid = threadIdx.x;
    const int j0 = blockIdx.x * 128;

    for (int idx = tid; idx < 128 * 128; idx += 256) {
        int j = idx >> 7, k = idx & 127;
        xsT[k * 132 + j] = x[(size_t)(j0 + j) * DF + k];
        Ws[idx] = W[idx];
    }
    __syncthreads();

    const int tx = tid & 15, ty = tid >> 4;
    const int jb = ty * 8, db = tx * 8;
    float acc[8][8];
#pragma unroll
    for (int a = 0; a < 8; a++)
#pragma unroll
        for (int b = 0; b < 8; b++) acc[a][b] = 0.0f;

    for (int k = 0; k < 128; k++) {
        float4 a0 = *(const float4*)(xsT + k * 132 + jb);
        float4 a1 = *(const float4*)(xsT + k * 132 + jb + 4);
        float4 b0 = *(const float4*)(Ws + k * 128 + db);
        float4 b1 = *(const float4*)(Ws + k * 128 + db + 4);
        float aa[8] = {a0.x, a0.y, a0.z, a0.w, a1.x, a1.y, a1.z, a1.w};
        float bb[8] = {b0.x, b0.y, b0.z, b0.w, b1.x, b1.y, b1.z, b1.w};
#pragma unroll
        for (int jj = 0; jj < 8; jj++)
#pragma unroll
            for (int dd = 0; dd < 8; dd++) acc[jj][dd] += aa[jj] * bb[dd];
    }
    __syncthreads();   // done reading xsT/Ws; reuse as staging

    // scatter into fragment-plane staging: this CTA covers 64 pair-rows = 4 chunks
#pragma unroll
    for (int q = 0; q < 4; q++) {
        const int p_local = (jb >> 1) + q;          // 0..63
        const int c_local = p_local >> 4;           // chunk 0..3
        const int kk = p_local & 15;
        const int ks = kk >> 3, r8 = kk & 7;
        const int jh = r8 >> 2, tg = r8 & 3;
#pragma unroll
        for (int dd = 0; dd < 8; dd++) {
            const int n = db + dd;
            const int h = n >> 6, ni = (n >> 3) & 7, g = n & 7;
            const int lane = 4 * g + tg;
            const int j = jh * 2 + (ni >> 2);
            const int off = c_local * 2048 + (h * 2 + ks) * 512 + j * 128
                          + lane * 4 + (ni & 3);
            stage[off] = packh2(acc[2 * q][dd], acc[2 * q + 1][dd]);
        }
    }
    __syncthreads();

    // linear coalesced copy to global (4 chunks = 8192 u32 = 2048 uint4)
    uint4* dst = (uint4*)(g_XWf + (size_t)blockIdx.x * 8192);
    const uint4* srcv = (const uint4*)stage;
#pragma unroll
    for (int i = 0; i < 8; i++) dst[tid + i * 256] = srcv[tid + i * 256];
}

// ---------------- kernel 2: warp-specialized fused exp + softmax-GEMM ----------------
// 512 threads: tid<256 = MMA consumers (8 warps), tid>=256 = producers (A only).
// A ring: 8 stages (4 pairs) x [128 rows x 20 u32 fp16-pairs] = 10240B each.
// B: direct LDG.128 from L2-resident g_XWf planes (coalesced), register-pipelined.
#define SA2 20
#define A_STG_B  (128 * SA2 * 4)                 // 10240
#define A_OFF    0u
#define RS_OFF   (A_OFF + 8 * A_STG_B)           // 81920
#define BIAS_OFF (RS_OFF + 512)                  // 82432
#define FUSED_SMEM (BIAS_OFF + 512)              // 82944

__global__ void __launch_bounds__(512, 1) fused_kernel(const float* __restrict__ adj,
                                                       const float* __restrict__ bias,
                                                       float* __restrict__ out) {
    extern __shared__ char sm8[];
    float* rs = (float*)(sm8 + RS_OFF);
    float* bs = (float*)(sm8 + BIAS_OFF);

    const int tid = threadIdx.x;
    const int m0 = blockIdx.x * 128;

    if (tid < DF) bs[tid] = bias[tid];

    if (tid >= 256) {
        // ================= PRODUCERS (adj -> exp -> A ring) =================
        const int ptid = tid - 256;
        const int r = ptid >> 1;           // adj row within tile
        const int hf = ptid & 1;           // 16-float half of 32-col chunk
        const float* agsrc = adj + (size_t)(m0 + r) * N_ROWS + hf * 16;
        const uint32_t a_sts = (uint32_t)r * SA2 + hf * 8;   // u32 units

        float4 a0b[4], a1b[4];
        float rsum = 0.0f;

#define LDGA(cn, BUF) do {                                                       \
            const float* _p = agsrc + (size_t)(cn) * KC;                         \
            BUF[0] = *(const float4*)(_p);                                       \
            BUF[1] = *(const float4*)(_p + 4);                                   \
            BUF[2] = *(const float4*)(_p + 8);                                   \
            BUF[3] = *(const float4*)(_p + 12);                                  \
        } while (0)
#define STSA(BUF, S) do {                                                        \
            uint32_t pk[8];                                                      \
            _Pragma("unroll")                                                    \
            for (int q = 0; q < 4; q++) {                                        \
                float e0 = __expf(BUF[q].x), e1 = __expf(BUF[q].y);              \
                float e2 = __expf(BUF[q].z), e3 = __expf(BUF[q].w);              \
                rsum += (e0 + e1) + (e2 + e3);                                   \
                pk[2 * q]     = packh2(e0, e1);                                  \
                pk[2 * q + 1] = packh2(e2, e3);                                  \
            }                                                                    \
            uint32_t* As = (uint32_t*)(sm8 + A_OFF + (size_t)(S) * A_STG_B);     \
            *(uint4*)(As + a_sts)     = make_uint4(pk[0], pk[1], pk[2], pk[3]);  \
            *(uint4*)(As + a_sts + 4) = make_uint4(pk[4], pk[5], pk[6], pk[7]);  \
        } while (0)

        LDGA(0, a0b);
        LDGA(1, a1b);

        int p = 0;
        for (int pt = 0; pt < NPITER; ++pt) {
            if (pt >= NPAIR) bar_sync_named(5 + p);   // pair p slots free
            const int c0 = 2 * pt;
            STSA(a0b, 2 * p);
            if (c0 + 2 < NITER) LDGA(c0 + 2, a0b);
            STSA(a1b, 2 * p + 1);
            if (c0 + 3 < NITER) LDGA(c0 + 3, a1b);
            __threadfence_block();
            bar_arrive_named(1 + p);
            p = (p == NPAIR - 1) ? 0 : p + 1;
        }

        rsum += __shfl_xor_sync(0xffffffffu, rsum, 1);
        if (hf == 0) rs[r] = rsum;
        __syncthreads();
        // producers done (consumers do epilogue)
    } else {
        // ================= CONSUMERS =================
        const int wid = tid >> 5;
        const int lid = tid & 31;
        const int g = lid >> 2, tg = lid & 3;
        const int mB = (wid & 3) * 32;
        const int h  = wid >> 2;
        const int nB = h * 64;

        float acc[2][8][4];
#pragma unroll
        for (int i = 0; i < 2; i++)
#pragma unroll
            for (int j = 0; j < 8; j++)
#pragma unroll
                for (int c = 0; c < 4; c++) acc[i][j][c] = 0.0f;

        // B register pipeline: 2 buffers of 4 uint4; load half (c, ks)
        uint4 bq[2][4];
#define LDB(BUF, c, ks) do {                                                     \
            const uint4* _bp = (const uint4*)g_XWf + (size_t)(c) * 512           \
                               + ((h) * 2 + (ks)) * 128 + lid;                   \
            BUF[0] = __ldg(_bp);                                                 \
            BUF[1] = __ldg(_bp + 32);                                            \
            BUF[2] = __ldg(_bp + 64);                                            \
            BUF[3] = __ldg(_bp + 96);                                            \
        } while (0)

        LDB(bq[0], 0, 0);   // prologue: half index 0

        int p = 0;
        for (int pt = 0; pt < NPITER; ++pt) {
            bar_sync_named(1 + p);
#pragma unroll
            for (int half = 0; half < 2; half++) {
                const int it = 2 * pt + half;
                const int s = 2 * p + half;
                const uint32_t* As = (const uint32_t*)(sm8 + A_OFF + (size_t)s * A_STG_B);
#pragma unroll
                for (int ks = 0; ks < 2; ks++) {
                    const int hIdx = it * 2 + ks;
                    const int cur = hIdx & 1;
                    // prefetch next ks-half (distance 1)
                    int nh = hIdx + 1;
                    if (nh > 2 * NITER - 1) nh = 2 * NITER - 1;
                    LDB(bq[cur ^ 1], nh >> 1, nh & 1);

                    // A fragments (scalar LDS, conflict-free via SA2=20)
                    uint32_t af[2][4];
#pragma unroll
                    for (int mi = 0; mi < 2; mi++) {
                        const uint32_t* Ar = As + (mB + mi * 16 + g) * SA2 + ks * 8 + tg;
                        af[mi][0] = Ar[0];
                        af[mi][1] = Ar[8 * SA2];
                        af[mi][2] = Ar[4];
                        af[mi][3] = Ar[8 * SA2 + 4];
                    }
                    const uint32_t b0a[8] = {bq[cur][0].x, bq[cur][0].y, bq[cur][0].z, bq[cur][0].w,
                                             bq[cur][1].x, bq[cur][1].y, bq[cur][1].z, bq[cur][1].w};
                    const uint32_t b1a[8] = {bq[cur][2].x, bq[cur][2].y, bq[cur][2].z, bq[cur][2].w,
                                             bq[cur][3].x, bq[cur][3].y, bq[cur][3].z, bq[cur][3].w};
#pragma unroll
                    for (int ni = 0; ni < 8; ni++) {
#pragma unroll
                        for (int mi = 0; mi < 2; mi++) {
                            asm volatile(
                                "mma.sync.aligned.m16n8k16.row.col.f32.f16.f16.f32 "
                                "{%0,%1,%2,%3}, {%4,%5,%6,%7}, {%8,%9}, {%0,%1,%2,%3};"
                                : "+f"(acc[mi][ni][0]), "+f"(acc[mi][ni][1]),
                                  "+f"(acc[mi][ni][2]), "+f"(acc[mi][ni][3])
                                : "r"(af[mi][0]), "r"(af[mi][1]), "r"(af[mi][2]), "r"(af[mi][3]),
                                  "r"(b0a[ni]), "r"(b1a[ni]));
                        }
                    }
                }
            }
            bar_arrive_named(5 + p);
            p = (p == NPAIR - 1) ? 0 : p + 1;
        }

        __syncthreads();   // rowsums + bias visible

        // epilogue: divide + bias + store
#pragma unroll
        for (int mi = 0; mi < 2; mi++) {
            const int r0 = mB + mi * 16 + g;
            const int r1 = r0 + 8;
            const float inv0 = 1.0f / rs[r0];
            const float inv1 = 1.0f / rs[r1];
#pragma unroll
            for (int ni = 0; ni < 8; ni++) {
                const int c = nB + ni * 8 + 2 * tg;
                const float b0v = bs[c];
                const float b1v = bs[c + 1];
                float2 o;
                o.x = acc[mi][ni][0] * inv0 + b0v;
                o.y = acc[mi][ni][1] * inv0 + b1v;
                *(float2*)(out + (size_t)(m0 + r0) * DF + c) = o;
                o.x = acc[mi][ni][2] * inv1 + b0v;
                o.y = acc[mi][ni][3] * inv1 + b1v;
                *(float2*)(out + (size_t)(m0 + r1) * DF + c) = o;
            }
        }
    }
}

// ---------------- launcher ----------------
extern "C" void kernel_launch(void* const* d_in, const int* in_sizes, int n_in,
                              void* d_out, int out_size) {
    const float* x   = (const float*)d_in[0];
    const float* adj = (const float*)d_in[1];
    const float* W   = (const float*)d_in[2];
    const float* b   = (const float*)d_in[3];
    float* out = (float*)d_out;
    (void)in_sizes; (void)n_in; (void)out_size;

    cudaFuncSetAttribute(xw_kernel, cudaFuncAttributeMaxDynamicSharedMemorySize, XW_SMEM);
    cudaFuncSetAttribute(fused_kernel, cudaFuncAttributeMaxDynamicSharedMemorySize, FUSED_SMEM);

    xw_kernel<<<N_ROWS / 128, 256, XW_SMEM>>>(x, W);
    fused_kernel<<<N_ROWS / 128, 512, FUSED_SMEM>>>(adj, b, out);
}

// round 14
// speedup vs baseline: 1.1502x; 1.1475x over previous
#include <cuda_runtime.h>
#include <cuda_fp16.h>
#include <cstdint>

// ---------------- problem constants ----------------
#define N_ROWS 16384
#define DF     128
#define KC     32                 // K chunk per ring stage
#define NITER  (N_ROWS / KC)      // 512
#define NPITER (NITER / 2)        // 256 stage-pairs
#define NPAIR  4                  // ring = 4 pairs = 8 stages

// g_XWf: XW = x@W, fp16 pairs, fragment-plane layout per 32-k chunk (2048 u32 = 8KB):
//   chunk c, block (h,ks) = (h*2+ks)*512 u32; plane j (0..3) * 128; lane*4 + (ni&3)
//   j = jh*2 + (ni>>2), jh: 0 = b0 (pair rows ks*8+tg), 1 = b1 (pair rows ks*8+4+tg)
//   lane = 4*g + tg ; value = half2{XW[2p][n], XW[2p+1][n]}, n = h*64+ni*8+g
__device__ uint32_t g_XWf[(size_t)NITER * 2048];   // 4 MiB

__device__ __forceinline__ uint32_t packh2(float lo, float hi) {
    __half2 h = __floats2half2_rn(lo, hi);
    return *(uint32_t*)&h;
}
__device__ __forceinline__ uint32_t smem_u32(const void* p) {
    uint32_t a;
    asm("{ .reg .u64 t; cvta.to.shared.u64 t, %1; cvt.u32.u64 %0, t; }" : "=r"(a) : "l"(p));
    return a;
}
__device__ __forceinline__ void cp_async16(uint32_t dst, const void* src) {
    asm volatile("cp.async.cg.shared.global [%0], [%1], 16;" :: "r"(dst), "l"(src));
}
#define CP_COMMIT() asm volatile("cp.async.commit_group;" ::: "memory")
#define CP_WAIT(n)  asm volatile("cp.async.wait_group %0;" :: "n"(n) : "memory")

__device__ __forceinline__ void bar_sync_named(int id) {
    asm volatile("bar.sync %0, 512;" :: "r"(id) : "memory");
}
__device__ __forceinline__ void bar_arrive_named(int id) {
    asm volatile("bar.arrive %0, 512;" :: "r"(id) : "memory");
}
// barrier ids: FULL(p)=1+p (1..4), EMPTY(p)=5+p (5..8)

#define LDSM_X4(R, addr) \
    asm volatile("ldmatrix.sync.aligned.m8n8.x4.shared.b16 {%0,%1,%2,%3}, [%4];" \
        : "=r"((R)[0]), "=r"((R)[1]), "=r"((R)[2]), "=r"((R)[3]) : "r"(addr))

// ---------------- kernel 1: XW = x @ W, emitted in fragment-plane order ----------------
#define XW_SMEM ((128 * 132 + 128 * 128) * 4)

__global__ void __launch_bounds__(256) xw_kernel(const float* __restrict__ x,
                                                 const float* __restrict__ W) {
    extern __shared__ float sm_xw[];
    float* xsT = sm_xw;              // [128][132] transposed x tile
    float* Ws  = sm_xw + 128 * 132;  // [128][128]
    uint32_t* stage = (uint32_t*)sm_xw;  // 8192 u32 staging (reused after compute)
    const int tid = threadIdx.x;
    const int j0 = blockIdx.x * 128;

    for (int idx = tid; idx < 128 * 128; idx += 256) {
        int j = idx >> 7, k = idx & 127;
        xsT[k * 132 + j] = x[(size_t)(j0 + j) * DF + k];
        Ws[idx] = W[idx];
    }
    __syncthreads();

    const int tx = tid & 15, ty = tid >> 4;
    const int jb = ty * 8, db = tx * 8;
    float acc[8][8];
#pragma unroll
    for (int a = 0; a < 8; a++)
#pragma unroll
        for (int b = 0; b < 8; b++) acc[a][b] = 0.0f;

    for (int k = 0; k < 128; k++) {
        float4 a0 = *(const float4*)(xsT + k * 132 + jb);
        float4 a1 = *(const float4*)(xsT + k * 132 + jb + 4);
        float4 b0 = *(const float4*)(Ws + k * 128 + db);
        float4 b1 = *(const float4*)(Ws + k * 128 + db + 4);
        float aa[8] = {a0.x, a0.y, a0.z, a0.w, a1.x, a1.y, a1.z, a1.w};
        float bb[8] = {b0.x, b0.y, b0.z, b0.w, b1.x, b1.y, b1.z, b1.w};
#pragma unroll
        for (int jj = 0; jj < 8; jj++)
#pragma unroll
            for (int dd = 0; dd < 8; dd++) acc[jj][dd] += aa[jj] * bb[dd];
    }
    __syncthreads();   // done reading xsT/Ws; reuse as staging

    // scatter into fragment-plane staging: this CTA covers 64 pair-rows = 4 chunks
#pragma unroll
    for (int q = 0; q < 4; q++) {
        const int p_local = (jb >> 1) + q;          // 0..63
        const int c_local = p_local >> 4;           // chunk 0..3
        const int kk = p_local & 15;
        const int ks = kk >> 3, r8 = kk & 7;
        const int jh = r8 >> 2, tg = r8 & 3;
#pragma unroll
        for (int dd = 0; dd < 8; dd++) {
            const int n = db + dd;
            const int h = n >> 6, ni = (n >> 3) & 7, g = n & 7;
            const int lane = 4 * g + tg;
            const int j = jh * 2 + (ni >> 2);
            const int off = c_local * 2048 + (h * 2 + ks) * 512 + j * 128
                          + lane * 4 + (ni & 3);
            stage[off] = packh2(acc[2 * q][dd], acc[2 * q + 1][dd]);
        }
    }
    __syncthreads();

    // linear coalesced copy to global (4 chunks = 8192 u32 = 2048 uint4)
    uint4* dst = (uint4*)(g_XWf + (size_t)blockIdx.x * 8192);
    const uint4* srcv = (const uint4*)stage;
#pragma unroll
    for (int i = 0; i < 8; i++) dst[tid + i * 256] = srcv[tid + i * 256];
}

// ---------------- kernel 2: warp-specialized fused exp + softmax-GEMM ----------------
// 512 threads: tid<256 = MMA consumers (8 warps), tid>=256 = producers.
// Ring: 8 stages (4 pairs) x { A: 128x20 u32 (10240B), B: 2048 u32 (8192B) }.
#define SA2 20
#define A_STG_B  (128 * SA2 * 4)                 // 10240
#define B_STG_B  8192
#define A_OFF    0u
#define B_OFF    (A_OFF + 8 * A_STG_B)           // 81920
#define RS_OFF   (B_OFF + 8 * B_STG_B)           // 147456
#define BIAS_OFF (RS_OFF + 512)                  // 147968
#define FUSED_SMEM (BIAS_OFF + 512)              // 148480

__global__ void __launch_bounds__(512, 1) fused_kernel(const float* __restrict__ adj,
                                                       const float* __restrict__ bias,
                                                       float* __restrict__ out) {
    extern __shared__ char sm8[];
    const uint32_t sb = smem_u32(sm8);
    float* rs = (float*)(sm8 + RS_OFF);
    float* bs = (float*)(sm8 + BIAS_OFF);

    const int tid = threadIdx.x;
    const int m0 = blockIdx.x * 128;

    if (tid < DF) bs[tid] = bias[tid];

    if (tid >= 256) {
        // ================= PRODUCERS =================
        const int ptid = tid - 256;
        const int r = ptid >> 1;           // adj row within tile
        const int hf = ptid & 1;           // 16-float half of 32-col chunk
        const float* agsrc = adj + (size_t)(m0 + r) * N_ROWS + hf * 16;
        const uint32_t a_sts = (uint32_t)r * SA2 + hf * 8;   // u32 units

        // B: linear 32B per thread per chunk
        const uint32_t* bgsrc = g_XWf + (size_t)ptid * 8;
        const uint32_t b_dst = sb + B_OFF + (uint32_t)ptid * 32;

        float4 a0b[4], a1b[4];
        float rsum = 0.0f;

#define LDGA(cn, BUF) do {                                                       \
            const float* _p = agsrc + (size_t)(cn) * KC;                         \
            BUF[0] = *(const float4*)(_p);                                       \
            BUF[1] = *(const float4*)(_p + 4);                                   \
            BUF[2] = *(const float4*)(_p + 8);                                   \
            BUF[3] = *(const float4*)(_p + 12);                                  \
        } while (0)
#define CPB(cn, S) do {                                                          \
            const uint32_t* _p = bgsrc + (size_t)(cn) * 2048;                    \
            uint32_t _d = b_dst + (uint32_t)(S) * B_STG_B;                       \
            cp_async16(_d,      _p);                                             \
            cp_async16(_d + 16, _p + 4);                                         \
        } while (0)
#define STSA(BUF, S) do {                                                        \
            uint32_t pk[8];                                                      \
            _Pragma("unroll")                                                    \
            for (int q = 0; q < 4; q++) {                                        \
                float e0 = __expf(BUF[q].x), e1 = __expf(BUF[q].y);              \
                float e2 = __expf(BUF[q].z), e3 = __expf(BUF[q].w);              \
                rsum += (e0 + e1) + (e2 + e3);                                   \
                pk[2 * q]     = packh2(e0, e1);                                  \
                pk[2 * q + 1] = packh2(e2, e3);                                  \
            }                                                                    \
            uint32_t* As = (uint32_t*)(sm8 + A_OFF + (size_t)(S) * A_STG_B);     \
            *(uint4*)(As + a_sts)     = make_uint4(pk[0], pk[1], pk[2], pk[3]);  \
            *(uint4*)(As + a_sts + 4) = make_uint4(pk[4], pk[5], pk[6], pk[7]);  \
        } while (0)

        LDGA(0, a0b);
        LDGA(1, a1b);
        // prologue: B for pair 0 into slots 0,1
        CPB(0, 0);
        CPB(1, 1);
        CP_COMMIT();

        int p = 0;
        for (int pt = 0; pt < NPITER; ++pt) {
            const int pn = (p == NPAIR - 1) ? 0 : p + 1;
            // issue B for NEXT pair (one pair ahead)
            if (pt + 1 < NPITER) {
                if (pt + 1 >= NPAIR) bar_sync_named(5 + pn);   // slots 2pn,2pn+1 free
                const int c0n = 2 * (pt + 1);
                CPB(c0n, 2 * pn);
                CPB(c0n + 1, 2 * pn + 1);
                CP_COMMIT();
            }
            // exp + STS this pair's A
            const int c0 = 2 * pt;
            STSA(a0b, 2 * p);
            if (c0 + 2 < NITER) LDGA(c0 + 2, a0b);
            STSA(a1b, 2 * p + 1);
            if (c0 + 3 < NITER) LDGA(c0 + 3, a1b);
            // B of THIS pair must be complete; next pair still in flight
            if (pt + 1 < NPITER) { CP_WAIT(1); } else { CP_WAIT(0); }
            __threadfence_block();
            bar_arrive_named(1 + p);
            p = pn;
        }

        rsum += __shfl_xor_sync(0xffffffffu, rsum, 1);
        if (hf == 0) rs[r] = rsum;
        __syncthreads();
        // producers done (consumers do epilogue)
    } else {
        // ================= CONSUMERS =================
        const int wid = tid >> 5;
        const int lid = tid & 31;
        const int g = lid >> 2, tg = lid & 3;
        const int mB = (wid & 3) * 32;
        const int h  = wid >> 2;
        const int nB = h * 64;

        // per-lane ldmatrix byte offset: row (lid&15), k-half (lid>>4)
        const uint32_t lds_lane = (uint32_t)((lid & 15) * (SA2 * 4) + (lid >> 4) * 16);

        float acc[2][8][4];
#pragma unroll
        for (int i = 0; i < 2; i++)
#pragma unroll
            for (int j = 0; j < 8; j++)
#pragma unroll
                for (int c = 0; c < 4; c++) acc[i][j][c] = 0.0f;

        int p = 0;
        for (int pt = 0; pt < NPITER; ++pt) {
            bar_sync_named(1 + p);
#pragma unroll
            for (int half = 0; half < 2; half++) {
                const int s = 2 * p + half;
                const uint32_t As_addr = sb + A_OFF + (uint32_t)s * A_STG_B;
                const uint32_t* Bs = (const uint32_t*)(sm8 + B_OFF + (size_t)s * B_STG_B);
#pragma unroll
                for (int ks = 0; ks < 2; ks++) {
                    uint32_t af[2][4];
#pragma unroll
                    for (int mi = 0; mi < 2; mi++) {
                        const uint32_t a_addr = As_addr
                            + (uint32_t)((mB + mi * 16) * (SA2 * 4)) + (uint32_t)(ks * 32)
                            + lds_lane;
                        LDSM_X4(af[mi], a_addr);
                    }
                    // B fragments: 4 conflict-free LDS.128 from plane layout
                    const uint32_t* Bb = Bs + (h * 2 + ks) * 512 + lid * 4;
                    const uint4 q0 = *(const uint4*)(Bb);          // b0, ni 0..3
                    const uint4 q1 = *(const uint4*)(Bb + 128);    // b0, ni 4..7
                    const uint4 q2 = *(const uint4*)(Bb + 256);    // b1, ni 0..3
                    const uint4 q3 = *(const uint4*)(Bb + 384);    // b1, ni 4..7
                    const uint32_t b0a[8] = {q0.x, q0.y, q0.z, q0.w, q1.x, q1.y, q1.z, q1.w};
                    const uint32_t b1a[8] = {q2.x, q2.y, q2.z, q2.w, q3.x, q3.y, q3.z, q3.w};
#pragma unroll
                    for (int ni = 0; ni < 8; ni++) {
#pragma unroll
                        for (int mi = 0; mi < 2; mi++) {
                            asm volatile(
                                "mma.sync.aligned.m16n8k16.row.col.f32.f16.f16.f32 "
                                "{%0,%1,%2,%3}, {%4,%5,%6,%7}, {%8,%9}, {%0,%1,%2,%3};"
                                : "+f"(acc[mi][ni][0]), "+f"(acc[mi][ni][1]),
                                  "+f"(acc[mi][ni][2]), "+f"(acc[mi][ni][3])
                                : "r"(af[mi][0]), "r"(af[mi][1]), "r"(af[mi][2]), "r"(af[mi][3]),
                                  "r"(b0a[ni]), "r"(b1a[ni]));
                        }
                    }
                }
            }
            bar_arrive_named(5 + p);
            p = (p == NPAIR - 1) ? 0 : p + 1;
        }

        __syncthreads();   // rowsums + bias visible

        // epilogue: divide + bias + store
#pragma unroll
        for (int mi = 0; mi < 2; mi++) {
            const int r0 = mB + mi * 16 + g;
            const int r1 = r0 + 8;
            const float inv0 = 1.0f / rs[r0];
            const float inv1 = 1.0f / rs[r1];
#pragma unroll
            for (int ni = 0; ni < 8; ni++) {
                const int c = nB + ni * 8 + 2 * tg;
                const float b0v = bs[c];
                const float b1v = bs[c + 1];
                float2 o;
                o.x = acc[mi][ni][0] * inv0 + b0v;
                o.y = acc[mi][ni][1] * inv0 + b1v;
                *(float2*)(out + (size_t)(m0 + r0) * DF + c) = o;
                o.x = acc[mi][ni][2] * inv1 + b0v;
                o.y = acc[mi][ni][3] * inv1 + b1v;
                *(float2*)(out + (size_t)(m0 + r1) * DF + c) = o;
            }
        }
    }
}

// ---------------- launcher ----------------
extern "C" void kernel_launch(void* const* d_in, const int* in_sizes, int n_in,
                              void* d_out, int out_size) {
    const float* x   = (const float*)d_in[0];
    const float* adj = (const float*)d_in[1];
    const float* W   = (const float*)d_in[2];
    const float* b   = (const float*)d_in[3];
    float* out = (float*)d_out;
    (void)in_sizes; (void)n_in; (void)out_size;

    cudaFuncSetAttribute(xw_kernel, cudaFuncAttributeMaxDynamicSharedMemorySize, XW_SMEM);
    cudaFuncSetAttribute(fused_kernel, cudaFuncAttributeMaxDynamicSharedMemorySize, FUSED_SMEM);

    xw_kernel<<<N_ROWS / 128, 256, XW_SMEM>>>(x, W);
    fused_kernel<<<N_ROWS / 128, 512, FUSED_SMEM>>>(adj, b, out);
}